// round 1
// baseline (speedup 1.0000x reference)
#include <cuda_runtime.h>
#include <math.h>

// ---------------- problem constants ----------------
#define BB       256
#define DMODEL   2048
#define DINNER   8192
#define DSTATE   16
#define DTRANK   128
#define XPN      (DTRANK + 2*DSTATE)   // 160

// ---------------- scratch (device globals; no allocation) ----------------
__device__ float g_xz [BB * 2 * DINNER];   // 256 x 16384  (xi | z)
__device__ float g_xc [BB * DINNER];       // post-conv SiLU
__device__ float g_xdb[BB * XPN];          // dt_in | Bm | Cm
__device__ float g_dt [BB * DINNER];       // softplus(dt)
__device__ float g_y  [BB * DINNER];       // pre-W_out activations
__device__ float g_A  [DINNER * DSTATE];   // A = -exp(A_log)

// ---------------- small helpers ----------------
__global__ void zero_kernel(float* __restrict__ p, int n) {
    int i = blockIdx.x * blockDim.x + threadIdx.x;
    if (i < n) p[i] = 0.0f;
}

__global__ void precompute_A_kernel(const float* __restrict__ A_log) {
    int i = blockIdx.x * blockDim.x + threadIdx.x;
    if (i < DINNER * DSTATE) g_A[i] = -expf(A_log[i]);
}

// ---------------- generic tiled SGEMM: C[M,N] = A[M,K] * B[N,K]^T ----------------
// Both operands K-contiguous (row-major, leading dim = lda/ldb).
// EPI: 0 = store, 1 = atomicAdd (split-K), 2 = softplus(acc + bias[n])
template<int BM, int BN, int BK, int TM, int TN, int EPI>
__global__ void __launch_bounds__((BM/TM)*(BN/TN))
sgemm_nt(const float* __restrict__ A, int lda,
         const float* __restrict__ Bm, int ldb,
         float* __restrict__ C, int ldc,
         int M, int N, int K, int kChunk,
         const float* __restrict__ bias)
{
    constexpr int THREADS = (BM/TM)*(BN/TN);
    constexpr int KQ = BK / 4;            // float4 quads along K
    constexpr int A4 = BM * BK / 4;
    constexpr int B4 = BN * BK / 4;

    __shared__ float As[BK][BM];
    __shared__ float Bs[BK][BN];

    const int tid = threadIdx.x;
    const int n0  = blockIdx.x * BN;
    const int m0  = blockIdx.y * BM;
    const int kb  = blockIdx.z * kChunk;
    const int ke  = (kb + kChunk < K) ? (kb + kChunk) : K;

    const int tc = tid % (BN / TN);
    const int tr = tid / (BN / TN);

    float acc[TM][TN];
    #pragma unroll
    for (int i = 0; i < TM; i++)
        #pragma unroll
        for (int j = 0; j < TN; j++) acc[i][j] = 0.0f;

    for (int k0 = kb; k0 < ke; k0 += BK) {
        // load A tile (BM x BK) transposed into As[BK][BM]
        #pragma unroll
        for (int i = tid; i < A4; i += THREADS) {
            int m  = i / KQ;
            int kq = i % KQ;
            float4 v = *(const float4*)&A[(size_t)(m0 + m) * lda + k0 + kq * 4];
            As[kq*4+0][m] = v.x; As[kq*4+1][m] = v.y;
            As[kq*4+2][m] = v.z; As[kq*4+3][m] = v.w;
        }
        // load B tile (BN x BK) transposed into Bs[BK][BN]
        #pragma unroll
        for (int i = tid; i < B4; i += THREADS) {
            int n  = i / KQ;
            int kq = i % KQ;
            float4 v = *(const float4*)&Bm[(size_t)(n0 + n) * ldb + k0 + kq * 4];
            Bs[kq*4+0][n] = v.x; Bs[kq*4+1][n] = v.y;
            Bs[kq*4+2][n] = v.z; Bs[kq*4+3][n] = v.w;
        }
        __syncthreads();

        #pragma unroll
        for (int kk = 0; kk < BK; kk++) {
            float a[TM], b[TN];
            #pragma unroll
            for (int i = 0; i < TM; i++) a[i] = As[kk][tr*TM + i];
            #pragma unroll
            for (int j = 0; j < TN; j++) b[j] = Bs[kk][tc*TN + j];
            #pragma unroll
            for (int i = 0; i < TM; i++)
                #pragma unroll
                for (int j = 0; j < TN; j++)
                    acc[i][j] = fmaf(a[i], b[j], acc[i][j]);
        }
        __syncthreads();
    }

    #pragma unroll
    for (int i = 0; i < TM; i++) {
        int m = m0 + tr*TM + i;
        #pragma unroll
        for (int j = 0; j < TN; j++) {
            int n = n0 + tc*TN + j;
            float v = acc[i][j];
            if (EPI == 0) {
                C[(size_t)m * ldc + n] = v;
            } else if (EPI == 1) {
                atomicAdd(&C[(size_t)m * ldc + n], v);
            } else { // softplus(acc + bias[n]) = max(x,0) + log1p(exp(-|x|))
                float x = v + bias[n];
                float r = fmaxf(x, 0.0f) + log1pf(__expf(-fabsf(x)));
                C[(size_t)m * ldc + n] = r;
            }
        }
    }
}

// ---------------- conv window shift + SiLU ----------------
__global__ void conv_kernel(const float* __restrict__ cs_in,
                            const float* __restrict__ conv_w,
                            const float* __restrict__ conv_b,
                            float* __restrict__ cs_out)
{
    int idx = blockIdx.x * blockDim.x + threadIdx.x;   // over B*DINNER
    int b = idx >> 13;            // / 8192
    int d = idx & (DINNER - 1);
    float4 cs = ((const float4*)cs_in)[idx];
    float4 w  = ((const float4*)conv_w)[d];
    float xi  = g_xz[(size_t)b * (2*DINNER) + d];
    float s = cs.y*w.x + cs.z*w.y + cs.w*w.z + xi*w.w + conv_b[d];
    float sig = 1.0f / (1.0f + __expf(-s));
    g_xc[idx] = s * sig;
    ((float4*)cs_out)[idx] = make_float4(cs.y, cs.z, cs.w, xi);
}

// ---------------- SSM state update + y ----------------
__global__ void ssm_kernel(const float* __restrict__ ssm_in,
                           const float* __restrict__ D_param,
                           float* __restrict__ ssm_out)
{
    __shared__ float bm[DSTATE], cm[DSTATE];
    const int b = blockIdx.y;
    const int d = blockIdx.x * blockDim.x + threadIdx.x;
    if (threadIdx.x < 2*DSTATE) {
        float v = g_xdb[b * XPN + DTRANK + threadIdx.x];
        if (threadIdx.x < DSTATE) bm[threadIdx.x] = v;
        else                      cm[threadIdx.x - DSTATE] = v;
    }
    __syncthreads();

    const int bd = b * DINNER + d;
    const float dtv = g_dt[bd];
    const float xcv = g_xc[bd];
    const float xdt = xcv * dtv;
    const size_t base = (size_t)bd * DSTATE;

    float yacc = 0.0f;
    #pragma unroll
    for (int n = 0; n < DSTATE; n += 4) {
        float4 a  = *(const float4*)&g_A[d * DSTATE + n];
        float4 st = *(const float4*)&ssm_in[base + n];
        float4 ns;
        ns.x = st.x * __expf(a.x * dtv) + xdt * bm[n+0];
        ns.y = st.y * __expf(a.y * dtv) + xdt * bm[n+1];
        ns.z = st.z * __expf(a.z * dtv) + xdt * bm[n+2];
        ns.w = st.w * __expf(a.w * dtv) + xdt * bm[n+3];
        yacc += ns.x * cm[n+0] + ns.y * cm[n+1] + ns.z * cm[n+2] + ns.w * cm[n+3];
        *(float4*)&ssm_out[base + n] = ns;
    }
    yacc += D_param[d] * xcv;
    float zv = g_xz[(size_t)b * (2*DINNER) + DINNER + d];
    yacc *= zv / (1.0f + __expf(-zv));
    g_y[bd] = yacc;
}

// ---------------- launch ----------------
extern "C" void kernel_launch(void* const* d_in, const int* in_sizes, int n_in,
                              void* d_out, int out_size)
{
    const float* x       = (const float*)d_in[0];
    const float* cs_in   = (const float*)d_in[1];
    const float* ssm_in  = (const float*)d_in[2];
    const float* W_in    = (const float*)d_in[3];
    const float* conv_w  = (const float*)d_in[4];
    const float* conv_b  = (const float*)d_in[5];
    const float* W_xproj = (const float*)d_in[6];
    const float* W_dt    = (const float*)d_in[7];
    const float* b_dt    = (const float*)d_in[8];
    const float* A_log   = (const float*)d_in[9];
    const float* D_param = (const float*)d_in[10];
    const float* W_out   = (const float*)d_in[11];

    float* out     = (float*)d_out;                       // 256*2048
    float* cs_out  = out + (size_t)BB * DMODEL;           // 256*8192*4
    float* ssm_out = cs_out + (size_t)BB * DINNER * 4;    // 256*8192*16

    void *p_xz, *p_xc, *p_xdb, *p_dt, *p_y;
    cudaGetSymbolAddress(&p_xz,  g_xz);
    cudaGetSymbolAddress(&p_xc,  g_xc);
    cudaGetSymbolAddress(&p_xdb, g_xdb);
    cudaGetSymbolAddress(&p_dt,  g_dt);
    cudaGetSymbolAddress(&p_y,   g_y);

    // zero split-K accumulation targets
    zero_kernel<<<(BB*XPN + 255)/256, 256>>>((float*)p_xdb, BB*XPN);
    zero_kernel<<<(BB*DMODEL + 255)/256, 256>>>(out, BB*DMODEL);
    precompute_A_kernel<<<(DINNER*DSTATE + 255)/256, 256>>>(A_log);

    // GEMM1: xz[256,16384] = x[256,2048] @ W_in[16384,2048]^T
    sgemm_nt<128,128,8,8,8,0><<<dim3(16384/128, BB/128, 1), 256>>>(
        x, DMODEL, W_in, DMODEL, (float*)p_xz, 2*DINNER,
        BB, 2*DINNER, DMODEL, DMODEL, nullptr);

    // conv + SiLU, writes conv_state output + g_xc
    conv_kernel<<<(BB*DINNER)/256, 256>>>(cs_in, conv_w, conv_b, cs_out);

    // GEMM3: x_db[256,160] = xc[256,8192] @ W_xproj[160,8192]^T  (split-K=8, atomic)
    sgemm_nt<64,32,8,4,4,1><<<dim3(XPN/32, BB/64, 8), 128>>>(
        (const float*)p_xc, DINNER, W_xproj, DINNER, (float*)p_xdb, XPN,
        BB, XPN, DINNER, DINNER/8, nullptr);

    // GEMM4: dt[256,8192] = softplus(x_db[:, :128] @ W_dt[8192,128]^T + b_dt)
    sgemm_nt<64,64,8,4,4,2><<<dim3(DINNER/64, BB/64, 1), 256>>>(
        (const float*)p_xdb, XPN, W_dt, DTRANK, (float*)p_dt, DINNER,
        BB, DINNER, DTRANK, DTRANK, b_dt);

    // SSM update + y (includes SiLU(z) gating), writes ssm_state output + g_y
    ssm_kernel<<<dim3(DINNER/256, BB), 256>>>(ssm_in, D_param, ssm_out);

    // GEMM6: out[256,2048] = y[256,8192] @ W_out[2048,8192]^T  (split-K=8, atomic)
    sgemm_nt<128,128,8,8,8,1><<<dim3(DMODEL/128, BB/128, 8), 256>>>(
        (const float*)p_y, DINNER, W_out, DINNER, out, DMODEL,
        BB, DMODEL, DINNER, DINNER/8, nullptr);
}

// round 4
// speedup vs baseline: 1.9263x; 1.9263x over previous
#include <cuda_runtime.h>
#include <cuda_bf16.h>
#include <math.h>
#include <cstdint>

// ---------------- problem constants ----------------
#define BB       256
#define DMODEL   2048
#define DINNER   8192
#define DSTATE   16
#define DTRANK   128
#define XPN      (DTRANK + 2*DSTATE)   // 160

// ---------------- scratch (device globals; no allocation) ----------------
__device__ float g_xz [BB * 2 * DINNER];   // xi | z
__device__ float g_xc [BB * DINNER];
__device__ float g_xdb[BB * XPN];
__device__ float g_dt [BB * DINNER];
__device__ float g_y  [BB * DINNER];
__device__ float g_A  [DINNER * DSTATE];

// ---------------- helpers ----------------
__device__ __forceinline__ uint32_t smem_u32(const void* p) {
    uint32_t a;
    asm("{ .reg .u64 t; cvta.to.shared.u64 t, %1; cvt.u32.u64 %0, t; }" : "=r"(a) : "l"(p));
    return a;
}

__device__ __forceinline__ void ldmx4(uint32_t* r, uint32_t addr) {
    asm volatile("ldmatrix.sync.aligned.m8n8.x4.shared.b16 {%0,%1,%2,%3}, [%4];"
        : "=r"(r[0]), "=r"(r[1]), "=r"(r[2]), "=r"(r[3]) : "r"(addr));
}

__device__ __forceinline__ void mma16816(float* d, const uint32_t* a, const uint32_t* b) {
    asm volatile(
        "mma.sync.aligned.m16n8k16.row.col.f32.bf16.bf16.f32 "
        "{%0,%1,%2,%3}, {%4,%5,%6,%7}, {%8,%9}, {%0,%1,%2,%3};"
        : "+f"(d[0]), "+f"(d[1]), "+f"(d[2]), "+f"(d[3])
        : "r"(a[0]), "r"(a[1]), "r"(a[2]), "r"(a[3]), "r"(b[0]), "r"(b[1]));
}

// split a float4 (4 consecutive-k fp32) into bf16 hi + bf16 lo, store 4 elems each
__device__ __forceinline__ void split_store(__nv_bfloat16* th, __nv_bfloat16* tl,
                                            const float4& v) {
    __nv_bfloat162 h01 = __floats2bfloat162_rn(v.x, v.y);
    __nv_bfloat162 h23 = __floats2bfloat162_rn(v.z, v.w);
    float lx = v.x - __bfloat162float(h01.x);
    float ly = v.y - __bfloat162float(h01.y);
    float lz = v.z - __bfloat162float(h23.x);
    float lw = v.w - __bfloat162float(h23.y);
    __nv_bfloat162 l01 = __floats2bfloat162_rn(lx, ly);
    __nv_bfloat162 l23 = __floats2bfloat162_rn(lz, lw);
    uint2 hp = make_uint2(*(uint32_t*)&h01, *(uint32_t*)&h23);
    uint2 lp = make_uint2(*(uint32_t*)&l01, *(uint32_t*)&l23);
    *(uint2*)th = hp;
    *(uint2*)tl = lp;
}

// ---------------- HMMA bf16 hi/lo GEMM:  C[M,N] (+)= A[M,K] * B[N,K]^T ------
// fp32 inputs, inline hi/lo split, 3-product compensation. Tile 128x128x32.
// EPI: 0 = store, 1 = atomicAdd (split-K)
template<int EPI, int SPLITK>
__global__ void __launch_bounds__(256, 1)
hmma_gemm(const float* __restrict__ A, int lda,
          const float* __restrict__ B, int ldb,
          float* __restrict__ C, int ldc, int K)
{
    constexpr int BM = 128, BN = 128, BK = 32;
    constexpr int SK = 40;               // padded stride (bf16 elems): conflict-free
    __shared__ __nv_bfloat16 sAh[BM*SK], sAl[BM*SK], sBh[BN*SK], sBl[BN*SK];

    const int tid  = threadIdx.x;
    const int n0   = blockIdx.x * BN;
    const int m0   = blockIdx.y * BM;
    const int kChunk = K / SPLITK;
    const int kb   = blockIdx.z * kChunk;
    const int iters = kChunk / BK;

    // ---- loader mapping: 2 threads per row, 16 k-elems each ----
    const int lrow = tid >> 1;
    const int lq   = (tid & 1) * 16;     // k offset within tile

    const float* gA = A + (size_t)(m0 + lrow) * lda + kb + lq;
    const float* gB = B + (size_t)(n0 + lrow) * ldb + kb + lq;

    float4 ra[4], rb[4];
    #pragma unroll
    for (int j = 0; j < 4; j++) {
        ra[j] = *(const float4*)(gA + j * 4);
        rb[j] = *(const float4*)(gB + j * 4);
    }

    // ---- warp/compute mapping: 2 (m) x 4 (n) warps, warp tile 64x32 ----
    const int w    = tid >> 5;
    const int lane = tid & 31;
    const int wm   = (w & 1) * 64;
    const int wn   = (w >> 1) * 32;
    const int g    = lane >> 3;          // ldmatrix matrix index
    const int rr   = lane & 7;

    const uint32_t uAh = smem_u32(sAh), uAl = smem_u32(sAl);
    const uint32_t uBh = smem_u32(sBh), uBl = smem_u32(sBl);

    float acc[4][4][4];
    #pragma unroll
    for (int i = 0; i < 4; i++)
        #pragma unroll
        for (int j = 0; j < 4; j++)
            #pragma unroll
            for (int c = 0; c < 4; c++) acc[i][j][c] = 0.0f;

    for (int it = 0; it < iters; ++it) {
        __syncthreads();   // prior compute done before overwrite
        #pragma unroll
        for (int j = 0; j < 4; j++) {
            split_store(&sAh[lrow*SK + lq + j*4], &sAl[lrow*SK + lq + j*4], ra[j]);
            split_store(&sBh[lrow*SK + lq + j*4], &sBl[lrow*SK + lq + j*4], rb[j]);
        }
        __syncthreads();

        if (it + 1 < iters) {
            gA += BK; gB += BK;
            #pragma unroll
            for (int j = 0; j < 4; j++) {
                ra[j] = *(const float4*)(gA + j * 4);
                rb[j] = *(const float4*)(gB + j * 4);
            }
        }

        #pragma unroll
        for (int ks = 0; ks < 2; ks++) {
            const int k16 = ks * 16;
            // ---- B fragments (4 n8 tiles, hi+lo) via 2x ldmatrix.x4 each ----
            uint32_t bh[4][2], bl[4][2];
            #pragma unroll
            for (int pi = 0; pi < 2; pi++) {
                int browb = wn + pi * 16 + (g & 1) * 8 + rr;
                int bcol  = k16 + (g >> 1) * 8;
                uint32_t off = (uint32_t)(browb * SK + bcol) * 2;
                uint32_t t[4];
                ldmx4(t, uBh + off);
                bh[pi*2+0][0] = t[0]; bh[pi*2+0][1] = t[2];
                bh[pi*2+1][0] = t[1]; bh[pi*2+1][1] = t[3];
                ldmx4(t, uBl + off);
                bl[pi*2+0][0] = t[0]; bl[pi*2+0][1] = t[2];
                bl[pi*2+1][0] = t[1]; bl[pi*2+1][1] = t[3];
            }
            // ---- A fragments + MMAs ----
            #pragma unroll
            for (int mi = 0; mi < 4; mi++) {
                int arow = wm + mi * 16 + (g & 1) * 8 + rr;
                int acol = k16 + (g >> 1) * 8;
                uint32_t off = (uint32_t)(arow * SK + acol) * 2;
                uint32_t ah[4], al[4];
                ldmx4(ah, uAh + off);
                ldmx4(al, uAl + off);
                #pragma unroll
                for (int ni = 0; ni < 4; ni++) {
                    mma16816(acc[mi][ni], ah, bh[ni]);
                    mma16816(acc[mi][ni], al, bh[ni]);
                    mma16816(acc[mi][ni], ah, bl[ni]);
                }
            }
        }
    }

    // ---- epilogue ----
    const int erow = lane >> 2;
    const int ecol = (lane & 3) * 2;
    #pragma unroll
    for (int mi = 0; mi < 4; mi++) {
        #pragma unroll
        for (int ni = 0; ni < 4; ni++) {
            int r0 = m0 + wm + mi * 16 + erow;
            int c0 = n0 + wn + ni * 8 + ecol;
            float* p0 = C + (size_t)r0 * ldc + c0;
            float* p1 = C + (size_t)(r0 + 8) * ldc + c0;
            if (EPI == 0) {
                *(float2*)p0 = make_float2(acc[mi][ni][0], acc[mi][ni][1]);
                *(float2*)p1 = make_float2(acc[mi][ni][2], acc[mi][ni][3]);
            } else {
                atomicAdd(p0,     acc[mi][ni][0]);
                atomicAdd(p0 + 1, acc[mi][ni][1]);
                atomicAdd(p1,     acc[mi][ni][2]);
                atomicAdd(p1 + 1, acc[mi][ni][3]);
            }
        }
    }
}

// ---------------- small helpers ----------------
__global__ void zero_kernel(float* __restrict__ p, int n) {
    int i = blockIdx.x * blockDim.x + threadIdx.x;
    if (i < n) p[i] = 0.0f;
}

__global__ void precompute_A_kernel(const float* __restrict__ A_log) {
    int i = blockIdx.x * blockDim.x + threadIdx.x;
    if (i < DINNER * DSTATE) g_A[i] = -expf(A_log[i]);
}

// ---------------- fp32 tiled SGEMM (small GEMMs) ----------------
template<int BM, int BN, int BK, int TM, int TN, int EPI>
__global__ void __launch_bounds__((BM/TM)*(BN/TN))
sgemm_nt(const float* __restrict__ A, int lda,
         const float* __restrict__ Bm, int ldb,
         float* __restrict__ C, int ldc,
         int M, int N, int K, int kChunk,
         const float* __restrict__ bias)
{
    constexpr int THREADS = (BM/TM)*(BN/TN);
    constexpr int KQ = BK / 4;
    constexpr int A4 = BM * BK / 4;
    constexpr int B4 = BN * BK / 4;

    __shared__ float As[BK][BM];
    __shared__ float Bs[BK][BN];

    const int tid = threadIdx.x;
    const int n0  = blockIdx.x * BN;
    const int m0  = blockIdx.y * BM;
    const int kb  = blockIdx.z * kChunk;
    const int ke  = (kb + kChunk < K) ? (kb + kChunk) : K;

    const int tc = tid % (BN / TN);
    const int tr = tid / (BN / TN);

    float acc[TM][TN];
    #pragma unroll
    for (int i = 0; i < TM; i++)
        #pragma unroll
        for (int j = 0; j < TN; j++) acc[i][j] = 0.0f;

    for (int k0 = kb; k0 < ke; k0 += BK) {
        #pragma unroll
        for (int i = tid; i < A4; i += THREADS) {
            int m  = i / KQ;
            int kq = i % KQ;
            float4 v = *(const float4*)&A[(size_t)(m0 + m) * lda + k0 + kq * 4];
            As[kq*4+0][m] = v.x; As[kq*4+1][m] = v.y;
            As[kq*4+2][m] = v.z; As[kq*4+3][m] = v.w;
        }
        #pragma unroll
        for (int i = tid; i < B4; i += THREADS) {
            int n  = i / KQ;
            int kq = i % KQ;
            float4 v = *(const float4*)&Bm[(size_t)(n0 + n) * ldb + k0 + kq * 4];
            Bs[kq*4+0][n] = v.x; Bs[kq*4+1][n] = v.y;
            Bs[kq*4+2][n] = v.z; Bs[kq*4+3][n] = v.w;
        }
        __syncthreads();

        #pragma unroll
        for (int kk = 0; kk < BK; kk++) {
            float a[TM], b[TN];
            #pragma unroll
            for (int i = 0; i < TM; i++) a[i] = As[kk][tr*TM + i];
            #pragma unroll
            for (int j = 0; j < TN; j++) b[j] = Bs[kk][tc*TN + j];
            #pragma unroll
            for (int i = 0; i < TM; i++)
                #pragma unroll
                for (int j = 0; j < TN; j++)
                    acc[i][j] = fmaf(a[i], b[j], acc[i][j]);
        }
        __syncthreads();
    }

    #pragma unroll
    for (int i = 0; i < TM; i++) {
        int m = m0 + tr*TM + i;
        #pragma unroll
        for (int j = 0; j < TN; j++) {
            int n = n0 + tc*TN + j;
            float v = acc[i][j];
            if (EPI == 0) {
                C[(size_t)m * ldc + n] = v;
            } else if (EPI == 1) {
                atomicAdd(&C[(size_t)m * ldc + n], v);
            } else {
                float x = v + bias[n];
                float r = fmaxf(x, 0.0f) + log1pf(__expf(-fabsf(x)));
                C[(size_t)m * ldc + n] = r;
            }
        }
    }
}

// ---------------- conv window shift + SiLU ----------------
__global__ void conv_kernel(const float* __restrict__ cs_in,
                            const float* __restrict__ conv_w,
                            const float* __restrict__ conv_b,
                            float* __restrict__ cs_out)
{
    int idx = blockIdx.x * blockDim.x + threadIdx.x;
    int b = idx >> 13;
    int d = idx & (DINNER - 1);
    float4 cs = ((const float4*)cs_in)[idx];
    float4 w  = ((const float4*)conv_w)[d];
    float xi  = g_xz[(size_t)b * (2*DINNER) + d];
    float s = cs.y*w.x + cs.z*w.y + cs.w*w.z + xi*w.w + conv_b[d];
    float sig = 1.0f / (1.0f + __expf(-s));
    g_xc[idx] = s * sig;
    ((float4*)cs_out)[idx] = make_float4(cs.y, cs.z, cs.w, xi);
}

// ---------------- SSM state update + y ----------------
__global__ void ssm_kernel(const float* __restrict__ ssm_in,
                           const float* __restrict__ D_param,
                           float* __restrict__ ssm_out)
{
    __shared__ float bm[DSTATE], cm[DSTATE];
    const int b = blockIdx.y;
    const int d = blockIdx.x * blockDim.x + threadIdx.x;
    if (threadIdx.x < 2*DSTATE) {
        float v = g_xdb[b * XPN + DTRANK + threadIdx.x];
        if (threadIdx.x < DSTATE) bm[threadIdx.x] = v;
        else                      cm[threadIdx.x - DSTATE] = v;
    }
    __syncthreads();

    const int bd = b * DINNER + d;
    const float dtv = g_dt[bd];
    const float xcv = g_xc[bd];
    const float xdt = xcv * dtv;
    const size_t base = (size_t)bd * DSTATE;

    float yacc = 0.0f;
    #pragma unroll
    for (int n = 0; n < DSTATE; n += 4) {
        float4 a  = *(const float4*)&g_A[d * DSTATE + n];
        float4 st = *(const float4*)&ssm_in[base + n];
        float4 ns;
        ns.x = st.x * __expf(a.x * dtv) + xdt * bm[n+0];
        ns.y = st.y * __expf(a.y * dtv) + xdt * bm[n+1];
        ns.z = st.z * __expf(a.z * dtv) + xdt * bm[n+2];
        ns.w = st.w * __expf(a.w * dtv) + xdt * bm[n+3];
        yacc += ns.x * cm[n+0] + ns.y * cm[n+1] + ns.z * cm[n+2] + ns.w * cm[n+3];
        *(float4*)&ssm_out[base + n] = ns;
    }
    yacc += D_param[d] * xcv;
    float zv = g_xz[(size_t)b * (2*DINNER) + DINNER + d];
    yacc *= zv / (1.0f + __expf(-zv));
    g_y[bd] = yacc;
}

// ---------------- launch ----------------
extern "C" void kernel_launch(void* const* d_in, const int* in_sizes, int n_in,
                              void* d_out, int out_size)
{
    const float* x       = (const float*)d_in[0];
    const float* cs_in   = (const float*)d_in[1];
    const float* ssm_in  = (const float*)d_in[2];
    const float* W_in    = (const float*)d_in[3];
    const float* conv_w  = (const float*)d_in[4];
    const float* conv_b  = (const float*)d_in[5];
    const float* W_xproj = (const float*)d_in[6];
    const float* W_dt    = (const float*)d_in[7];
    const float* b_dt    = (const float*)d_in[8];
    const float* A_log   = (const float*)d_in[9];
    const float* D_param = (const float*)d_in[10];
    const float* W_out   = (const float*)d_in[11];

    float* out     = (float*)d_out;
    float* cs_out  = out + (size_t)BB * DMODEL;
    float* ssm_out = cs_out + (size_t)BB * DINNER * 4;

    void *p_xz, *p_xc, *p_xdb, *p_dt, *p_y;
    cudaGetSymbolAddress(&p_xz,  g_xz);
    cudaGetSymbolAddress(&p_xc,  g_xc);
    cudaGetSymbolAddress(&p_xdb, g_xdb);
    cudaGetSymbolAddress(&p_dt,  g_dt);
    cudaGetSymbolAddress(&p_y,   g_y);

    // zero split-K accumulation targets
    zero_kernel<<<(BB*XPN + 255)/256, 256>>>((float*)p_xdb, BB*XPN);
    zero_kernel<<<(BB*DMODEL + 255)/256, 256>>>(out, BB*DMODEL);
    precompute_A_kernel<<<(DINNER*DSTATE + 255)/256, 256>>>(A_log);

    // GEMM1: xz[256,16384] = x @ W_in^T   (HMMA bf16 hi/lo)
    hmma_gemm<0,1><<<dim3((2*DINNER)/128, BB/128, 1), 256>>>(
        x, DMODEL, W_in, DMODEL, (float*)p_xz, 2*DINNER, DMODEL);

    // conv + SiLU
    conv_kernel<<<(BB*DINNER)/256, 256>>>(cs_in, conv_w, conv_b, cs_out);

    // GEMM3: x_db[256,160] = xc @ W_xproj^T  (fp32, split-K=8, atomic)
    sgemm_nt<64,32,8,4,4,1><<<dim3(XPN/32, BB/64, 8), 128>>>(
        (const float*)p_xc, DINNER, W_xproj, DINNER, (float*)p_xdb, XPN,
        BB, XPN, DINNER, DINNER/8, nullptr);

    // GEMM4: dt[256,8192] = softplus(x_db[:, :128] @ W_dt^T + b_dt)  (fp32)
    sgemm_nt<64,64,8,4,4,2><<<dim3(DINNER/64, BB/64, 1), 256>>>(
        (const float*)p_xdb, XPN, W_dt, DTRANK, (float*)p_dt, DINNER,
        BB, DINNER, DTRANK, DTRANK, b_dt);

    // SSM update + y
    ssm_kernel<<<dim3(DINNER/256, BB), 256>>>(ssm_in, D_param, ssm_out);

    // GEMM6: out[256,2048] = y @ W_out^T  (HMMA bf16 hi/lo, split-K=4, atomic)
    hmma_gemm<1,4><<<dim3(DMODEL/128, BB/128, 4), 256>>>(
        (const float*)p_y, DINNER, W_out, DINNER, out, DMODEL, DINNER);
}

// round 5
// speedup vs baseline: 2.0501x; 1.0642x over previous
#include <cuda_runtime.h>
#include <cuda_bf16.h>
#include <math.h>
#include <cstdint>

// ---------------- problem constants ----------------
#define BB       256
#define DMODEL   2048
#define DINNER   8192
#define DSTATE   16
#define DTRANK   128
#define XPN      (DTRANK + 2*DSTATE)   // 160

// ---------------- scratch (device globals; no allocation) ----------------
__device__ float g_xz [BB * 2 * DINNER];   // xi | z
__device__ float g_xc [BB * DINNER];
__device__ float g_xdb[BB * XPN];
__device__ float g_dt [BB * DINNER];
__device__ float g_y  [BB * DINNER];
__device__ float g_A  [DINNER * DSTATE];

// ---------------- helpers ----------------
__device__ __forceinline__ uint32_t smem_u32(const void* p) {
    uint32_t a;
    asm("{ .reg .u64 t; cvta.to.shared.u64 t, %1; cvt.u32.u64 %0, t; }" : "=r"(a) : "l"(p));
    return a;
}

__device__ __forceinline__ void ldmx4(uint32_t* r, uint32_t addr) {
    asm volatile("ldmatrix.sync.aligned.m8n8.x4.shared.b16 {%0,%1,%2,%3}, [%4];"
        : "=r"(r[0]), "=r"(r[1]), "=r"(r[2]), "=r"(r[3]) : "r"(addr));
}

__device__ __forceinline__ void mma16816(float* d, const uint32_t* a, const uint32_t* b) {
    asm volatile(
        "mma.sync.aligned.m16n8k16.row.col.f32.bf16.bf16.f32 "
        "{%0,%1,%2,%3}, {%4,%5,%6,%7}, {%8,%9}, {%0,%1,%2,%3};"
        : "+f"(d[0]), "+f"(d[1]), "+f"(d[2]), "+f"(d[3])
        : "r"(a[0]), "r"(a[1]), "r"(a[2]), "r"(a[3]), "r"(b[0]), "r"(b[1]));
}

// split a float4 (4 consecutive-k fp32) into bf16 hi + bf16 lo, store 4 elems each
__device__ __forceinline__ void split_store(__nv_bfloat16* th, __nv_bfloat16* tl,
                                            const float4& v) {
    __nv_bfloat162 h01 = __floats2bfloat162_rn(v.x, v.y);
    __nv_bfloat162 h23 = __floats2bfloat162_rn(v.z, v.w);
    float lx = v.x - __bfloat162float(h01.x);
    float ly = v.y - __bfloat162float(h01.y);
    float lz = v.z - __bfloat162float(h23.x);
    float lw = v.w - __bfloat162float(h23.y);
    __nv_bfloat162 l01 = __floats2bfloat162_rn(lx, ly);
    __nv_bfloat162 l23 = __floats2bfloat162_rn(lz, lw);
    uint2 hp = make_uint2(*(uint32_t*)&h01, *(uint32_t*)&h23);
    uint2 lp = make_uint2(*(uint32_t*)&l01, *(uint32_t*)&l23);
    *(uint2*)th = hp;
    *(uint2*)tl = lp;
}

// ---------------- HMMA bf16 hi/lo GEMM:  C[M,N] (+)= A[M,K] * B[N,K]^T ------
// fp32 inputs, inline hi/lo split, 3-product compensation. Tile 128x128x32.
// Double-buffered smem pipeline, one __syncthreads per K-iter.
// EPI: 0 = store, 1 = atomicAdd (split-K)
#define GBM 128
#define GBN 128
#define GBK 32
#define GSK 40                         // padded bf16 stride
#define STAGE_ELEMS (4 * GBM * GSK)    // sAh|sAl|sBh|sBl per stage
#define STAGE_BYTES (STAGE_ELEMS * 2)

template<int EPI, int SPLITK>
__global__ void __launch_bounds__(256, 1)
hmma_gemm(const float* __restrict__ A, int lda,
          const float* __restrict__ B, int ldb,
          float* __restrict__ C, int ldc, int K)
{
    extern __shared__ __nv_bfloat16 sm[];

    const int tid  = threadIdx.x;
    const int n0   = blockIdx.x * GBN;
    const int m0   = blockIdx.y * GBM;
    const int kChunk = K / SPLITK;
    const int kb   = blockIdx.z * kChunk;
    const int iters = kChunk / GBK;

    // ---- loader mapping: 2 threads per row, 16 k-elems each ----
    const int lrow = tid >> 1;
    const int lq   = (tid & 1) * 16;

    const float* gA = A + (size_t)(m0 + lrow) * lda + kb + lq;
    const float* gB = B + (size_t)(n0 + lrow) * ldb + kb + lq;

    float4 ra[4], rb[4];
    #pragma unroll
    for (int j = 0; j < 4; j++) {
        ra[j] = *(const float4*)(gA + j * 4);
        rb[j] = *(const float4*)(gB + j * 4);
    }

    // store iter-0 regs into stage 0
    {
        __nv_bfloat16* st = sm;
        #pragma unroll
        for (int j = 0; j < 4; j++) {
            split_store(st + lrow*GSK + lq + j*4,
                        st + GBM*GSK + lrow*GSK + lq + j*4, ra[j]);
            split_store(st + 2*GBM*GSK + lrow*GSK + lq + j*4,
                        st + 2*GBM*GSK + GBN*GSK + lrow*GSK + lq + j*4, rb[j]);
        }
    }
    // prefetch iter 1
    if (iters > 1) {
        gA += GBK; gB += GBK;
        #pragma unroll
        for (int j = 0; j < 4; j++) {
            ra[j] = *(const float4*)(gA + j * 4);
            rb[j] = *(const float4*)(gB + j * 4);
        }
    }

    // ---- warp/compute mapping: 2 (m) x 4 (n) warps, warp tile 64x32 ----
    const int w    = tid >> 5;
    const int lane = tid & 31;
    const int wm   = (w & 1) * 64;
    const int wn   = (w >> 1) * 32;
    const int g    = lane >> 3;
    const int rr   = lane & 7;

    const uint32_t usm = smem_u32(sm);

    float acc[4][4][4];
    #pragma unroll
    for (int i = 0; i < 4; i++)
        #pragma unroll
        for (int j = 0; j < 4; j++)
            #pragma unroll
            for (int c = 0; c < 4; c++) acc[i][j][c] = 0.0f;

    __syncthreads();

    for (int it = 0; it < iters; ++it) {
        const int s = it & 1;

        // (a) fire-and-forget STS of iter it+1 into stage s^1
        if (it + 1 < iters) {
            __nv_bfloat16* st = sm + (size_t)(s ^ 1) * STAGE_ELEMS;
            #pragma unroll
            for (int j = 0; j < 4; j++) {
                split_store(st + lrow*GSK + lq + j*4,
                            st + GBM*GSK + lrow*GSK + lq + j*4, ra[j]);
                split_store(st + 2*GBM*GSK + lrow*GSK + lq + j*4,
                            st + 2*GBM*GSK + GBN*GSK + lrow*GSK + lq + j*4, rb[j]);
            }
        }
        // (b) LDG prefetch for iter it+2
        if (it + 2 < iters) {
            gA += GBK; gB += GBK;
            #pragma unroll
            for (int j = 0; j < 4; j++) {
                ra[j] = *(const float4*)(gA + j * 4);
                rb[j] = *(const float4*)(gB + j * 4);
            }
        }

        // (c) compute from stage s
        const uint32_t uS  = usm + (uint32_t)s * STAGE_BYTES;
        const uint32_t uAh = uS;
        const uint32_t uAl = uS + GBM*GSK*2;
        const uint32_t uBh = uS + 2*GBM*GSK*2;
        const uint32_t uBl = uS + (2*GBM*GSK + GBN*GSK)*2;

        #pragma unroll
        for (int ks = 0; ks < 2; ks++) {
            const int k16 = ks * 16;
            uint32_t bh[4][2], bl[4][2];
            #pragma unroll
            for (int pi = 0; pi < 2; pi++) {
                int browb = wn + pi * 16 + (g & 1) * 8 + rr;
                int bcol  = k16 + (g >> 1) * 8;
                uint32_t off = (uint32_t)(browb * GSK + bcol) * 2;
                uint32_t t[4];
                ldmx4(t, uBh + off);
                bh[pi*2+0][0] = t[0]; bh[pi*2+0][1] = t[2];
                bh[pi*2+1][0] = t[1]; bh[pi*2+1][1] = t[3];
                ldmx4(t, uBl + off);
                bl[pi*2+0][0] = t[0]; bl[pi*2+0][1] = t[2];
                bl[pi*2+1][0] = t[1]; bl[pi*2+1][1] = t[3];
            }
            #pragma unroll
            for (int mi = 0; mi < 4; mi++) {
                int arow = wm + mi * 16 + (g & 1) * 8 + rr;
                int acol = k16 + (g >> 1) * 8;
                uint32_t off = (uint32_t)(arow * GSK + acol) * 2;
                uint32_t ah[4], al[4];
                ldmx4(ah, uAh + off);
                ldmx4(al, uAl + off);
                #pragma unroll
                for (int ni = 0; ni < 4; ni++) {
                    mma16816(acc[mi][ni], ah, bh[ni]);
                    mma16816(acc[mi][ni], al, bh[ni]);
                    mma16816(acc[mi][ni], ah, bl[ni]);
                }
            }
        }
        __syncthreads();
    }

    // ---- epilogue ----
    const int erow = lane >> 2;
    const int ecol = (lane & 3) * 2;
    #pragma unroll
    for (int mi = 0; mi < 4; mi++) {
        #pragma unroll
        for (int ni = 0; ni < 4; ni++) {
            int r0 = m0 + wm + mi * 16 + erow;
            int c0 = n0 + wn + ni * 8 + ecol;
            float* p0 = C + (size_t)r0 * ldc + c0;
            float* p1 = C + (size_t)(r0 + 8) * ldc + c0;
            if (EPI == 0) {
                *(float2*)p0 = make_float2(acc[mi][ni][0], acc[mi][ni][1]);
                *(float2*)p1 = make_float2(acc[mi][ni][2], acc[mi][ni][3]);
            } else {
                atomicAdd(p0,     acc[mi][ni][0]);
                atomicAdd(p0 + 1, acc[mi][ni][1]);
                atomicAdd(p1,     acc[mi][ni][2]);
                atomicAdd(p1 + 1, acc[mi][ni][3]);
            }
        }
    }
}

// ---------------- small helpers ----------------
__global__ void zero_kernel(float* __restrict__ p, int n) {
    int i = blockIdx.x * blockDim.x + threadIdx.x;
    if (i < n) p[i] = 0.0f;
}

__global__ void precompute_A_kernel(const float* __restrict__ A_log) {
    int i = blockIdx.x * blockDim.x + threadIdx.x;
    if (i < DINNER * DSTATE) g_A[i] = -expf(A_log[i]);
}

// ---------------- fp32 tiled SGEMM (small GEMMs) ----------------
template<int BM, int BN, int BK, int TM, int TN, int EPI>
__global__ void __launch_bounds__((BM/TM)*(BN/TN))
sgemm_nt(const float* __restrict__ A, int lda,
         const float* __restrict__ Bm, int ldb,
         float* __restrict__ C, int ldc,
         int M, int N, int K, int kChunk,
         const float* __restrict__ bias)
{
    constexpr int THREADS = (BM/TM)*(BN/TN);
    constexpr int KQ = BK / 4;
    constexpr int A4 = BM * BK / 4;
    constexpr int B4 = BN * BK / 4;

    __shared__ float As[BK][BM];
    __shared__ float Bs[BK][BN];

    const int tid = threadIdx.x;
    const int n0  = blockIdx.x * BN;
    const int m0  = blockIdx.y * BM;
    const int kb  = blockIdx.z * kChunk;
    const int ke  = (kb + kChunk < K) ? (kb + kChunk) : K;

    const int tc = tid % (BN / TN);
    const int tr = tid / (BN / TN);

    float acc[TM][TN];
    #pragma unroll
    for (int i = 0; i < TM; i++)
        #pragma unroll
        for (int j = 0; j < TN; j++) acc[i][j] = 0.0f;

    for (int k0 = kb; k0 < ke; k0 += BK) {
        #pragma unroll
        for (int i = tid; i < A4; i += THREADS) {
            int m  = i / KQ;
            int kq = i % KQ;
            float4 v = *(const float4*)&A[(size_t)(m0 + m) * lda + k0 + kq * 4];
            As[kq*4+0][m] = v.x; As[kq*4+1][m] = v.y;
            As[kq*4+2][m] = v.z; As[kq*4+3][m] = v.w;
        }
        #pragma unroll
        for (int i = tid; i < B4; i += THREADS) {
            int n  = i / KQ;
            int kq = i % KQ;
            float4 v = *(const float4*)&Bm[(size_t)(n0 + n) * ldb + k0 + kq * 4];
            Bs[kq*4+0][n] = v.x; Bs[kq*4+1][n] = v.y;
            Bs[kq*4+2][n] = v.z; Bs[kq*4+3][n] = v.w;
        }
        __syncthreads();

        #pragma unroll
        for (int kk = 0; kk < BK; kk++) {
            float a[TM], b[TN];
            #pragma unroll
            for (int i = 0; i < TM; i++) a[i] = As[kk][tr*TM + i];
            #pragma unroll
            for (int j = 0; j < TN; j++) b[j] = Bs[kk][tc*TN + j];
            #pragma unroll
            for (int i = 0; i < TM; i++)
                #pragma unroll
                for (int j = 0; j < TN; j++)
                    acc[i][j] = fmaf(a[i], b[j], acc[i][j]);
        }
        __syncthreads();
    }

    #pragma unroll
    for (int i = 0; i < TM; i++) {
        int m = m0 + tr*TM + i;
        #pragma unroll
        for (int j = 0; j < TN; j++) {
            int n = n0 + tc*TN + j;
            float v = acc[i][j];
            if (EPI == 0) {
                C[(size_t)m * ldc + n] = v;
            } else if (EPI == 1) {
                atomicAdd(&C[(size_t)m * ldc + n], v);
            } else {
                float x = v + bias[n];
                float r = fmaxf(x, 0.0f) + log1pf(__expf(-fabsf(x)));
                C[(size_t)m * ldc + n] = r;
            }
        }
    }
}

// ---------------- conv window shift + SiLU ----------------
__global__ void conv_kernel(const float* __restrict__ cs_in,
                            const float* __restrict__ conv_w,
                            const float* __restrict__ conv_b,
                            float* __restrict__ cs_out)
{
    int idx = blockIdx.x * blockDim.x + threadIdx.x;
    int b = idx >> 13;
    int d = idx & (DINNER - 1);
    float4 cs = ((const float4*)cs_in)[idx];
    float4 w  = ((const float4*)conv_w)[d];
    float xi  = g_xz[(size_t)b * (2*DINNER) + d];
    float s = cs.y*w.x + cs.z*w.y + cs.w*w.z + xi*w.w + conv_b[d];
    float sig = 1.0f / (1.0f + __expf(-s));
    g_xc[idx] = s * sig;
    ((float4*)cs_out)[idx] = make_float4(cs.y, cs.z, cs.w, xi);
}

// ---------------- SSM state update + y ----------------
__global__ void ssm_kernel(const float* __restrict__ ssm_in,
                           const float* __restrict__ D_param,
                           float* __restrict__ ssm_out)
{
    __shared__ float bm[DSTATE], cm[DSTATE];
    const int b = blockIdx.y;
    const int d = blockIdx.x * blockDim.x + threadIdx.x;
    if (threadIdx.x < 2*DSTATE) {
        float v = g_xdb[b * XPN + DTRANK + threadIdx.x];
        if (threadIdx.x < DSTATE) bm[threadIdx.x] = v;
        else                      cm[threadIdx.x - DSTATE] = v;
    }
    __syncthreads();

    const int bd = b * DINNER + d;
    const float dtv = g_dt[bd];
    const float xcv = g_xc[bd];
    const float xdt = xcv * dtv;
    const size_t base = (size_t)bd * DSTATE;

    float yacc = 0.0f;
    #pragma unroll
    for (int n = 0; n < DSTATE; n += 4) {
        float4 a  = *(const float4*)&g_A[d * DSTATE + n];
        float4 st = *(const float4*)&ssm_in[base + n];
        float4 ns;
        ns.x = st.x * __expf(a.x * dtv) + xdt * bm[n+0];
        ns.y = st.y * __expf(a.y * dtv) + xdt * bm[n+1];
        ns.z = st.z * __expf(a.z * dtv) + xdt * bm[n+2];
        ns.w = st.w * __expf(a.w * dtv) + xdt * bm[n+3];
        yacc += ns.x * cm[n+0] + ns.y * cm[n+1] + ns.z * cm[n+2] + ns.w * cm[n+3];
        *(float4*)&ssm_out[base + n] = ns;
    }
    yacc += D_param[d] * xcv;
    float zv = g_xz[(size_t)b * (2*DINNER) + DINNER + d];
    yacc *= zv / (1.0f + __expf(-zv));
    g_y[bd] = yacc;
}

// ---------------- launch ----------------
extern "C" void kernel_launch(void* const* d_in, const int* in_sizes, int n_in,
                              void* d_out, int out_size)
{
    const float* x       = (const float*)d_in[0];
    const float* cs_in   = (const float*)d_in[1];
    const float* ssm_in  = (const float*)d_in[2];
    const float* W_in    = (const float*)d_in[3];
    const float* conv_w  = (const float*)d_in[4];
    const float* conv_b  = (const float*)d_in[5];
    const float* W_xproj = (const float*)d_in[6];
    const float* W_dt    = (const float*)d_in[7];
    const float* b_dt    = (const float*)d_in[8];
    const float* A_log   = (const float*)d_in[9];
    const float* D_param = (const float*)d_in[10];
    const float* W_out   = (const float*)d_in[11];

    float* out     = (float*)d_out;
    float* cs_out  = out + (size_t)BB * DMODEL;
    float* ssm_out = cs_out + (size_t)BB * DINNER * 4;

    void *p_xz, *p_xc, *p_xdb, *p_dt, *p_y;
    cudaGetSymbolAddress(&p_xz,  g_xz);
    cudaGetSymbolAddress(&p_xc,  g_xc);
    cudaGetSymbolAddress(&p_xdb, g_xdb);
    cudaGetSymbolAddress(&p_dt,  g_dt);
    cudaGetSymbolAddress(&p_y,   g_y);

    const int HSM = 2 * STAGE_BYTES;   // 81920 bytes
    cudaFuncSetAttribute(hmma_gemm<0,1>, cudaFuncAttributeMaxDynamicSharedMemorySize, HSM);
    cudaFuncSetAttribute(hmma_gemm<1,4>, cudaFuncAttributeMaxDynamicSharedMemorySize, HSM);

    // zero split-K accumulation targets
    zero_kernel<<<(BB*XPN + 255)/256, 256>>>((float*)p_xdb, BB*XPN);
    zero_kernel<<<(BB*DMODEL + 255)/256, 256>>>(out, BB*DMODEL);
    precompute_A_kernel<<<(DINNER*DSTATE + 255)/256, 256>>>(A_log);

    // GEMM1: xz[256,16384] = x @ W_in^T   (HMMA bf16 hi/lo, pipelined)
    hmma_gemm<0,1><<<dim3((2*DINNER)/GBN, BB/GBM, 1), 256, HSM>>>(
        x, DMODEL, W_in, DMODEL, (float*)p_xz, 2*DINNER, DMODEL);

    // conv + SiLU
    conv_kernel<<<(BB*DINNER)/256, 256>>>(cs_in, conv_w, conv_b, cs_out);

    // GEMM3: x_db[256,160] = xc @ W_xproj^T  (fp32, split-K=8, atomic)
    sgemm_nt<64,32,8,4,4,1><<<dim3(XPN/32, BB/64, 8), 128>>>(
        (const float*)p_xc, DINNER, W_xproj, DINNER, (float*)p_xdb, XPN,
        BB, XPN, DINNER, DINNER/8, nullptr);

    // GEMM4: dt[256,8192] = softplus(x_db[:, :128] @ W_dt^T + b_dt)  (fp32)
    sgemm_nt<64,64,8,4,4,2><<<dim3(DINNER/64, BB/64, 1), 256>>>(
        (const float*)p_xdb, XPN, W_dt, DTRANK, (float*)p_dt, DINNER,
        BB, DINNER, DTRANK, DTRANK, b_dt);

    // SSM update + y
    ssm_kernel<<<dim3(DINNER/256, BB), 256>>>(ssm_in, D_param, ssm_out);

    // GEMM6: out[256,2048] = y @ W_out^T  (HMMA bf16 hi/lo, split-K=4, atomic)
    hmma_gemm<1,4><<<dim3(DMODEL/GBN, BB/GBM, 4), 256, HSM>>>(
        (const float*)p_y, DINNER, W_out, DINNER, out, DMODEL, DINNER);
}